// round 8
// baseline (speedup 1.0000x reference)
#include <cuda_runtime.h>
#include <cuda_bf16.h>
#include <cstdint>
#include <cstddef>

typedef unsigned long long ull;
typedef unsigned int u32;

#define BB 32
#define TT 1024
#define HH 512
#define GG 2048
#define NCTA 128            // lstm CTAs
#define PKP 520             // packed h image pitch (words): 512 + 8

// ---------------- device scratch (allocations are forbidden) ----------------
__device__ __align__(16) float g_xp[(size_t)TT * GG * BB];   // x_proj[t][g][b]
__device__ __align__(16) u32 g_hpk[2][32 * PKP];             // packed (hi,lo) h images
__device__ __align__(128) unsigned g_flags[NCTA * 8];

// ---------------- helpers ----------------
__device__ __forceinline__ ull fadd2(ull a, ull b) {
    ull d; asm("add.rn.f32x2 %0, %1, %2;" : "=l"(d) : "l"(a), "l"(b)); return d;
}
__device__ __forceinline__ ull pack2(float x, float y) {
    ull d; asm("mov.b64 %0, {%1, %2};" : "=l"(d) : "f"(x), "f"(y)); return d;
}
__device__ __forceinline__ float sigm(float x) { return __fdividef(1.0f, 1.0f + __expf(-x)); }
__device__ __forceinline__ float tanh_(float x) { return 1.0f - __fdividef(2.0f, __expf(2.0f * x) + 1.0f); }

__device__ __forceinline__ u32 pack_bf2(float a, float b) {
    return (u32)__bfloat16_as_ushort(__float2bfloat16(a))
         | ((u32)__bfloat16_as_ushort(__float2bfloat16(b)) << 16);
}
__device__ __forceinline__ void mma16816(float& c0, float& c1, float& c2, float& c3,
                                         u32 a0, u32 a1, u32 a2, u32 a3, u32 b0, u32 b1) {
    asm volatile(
        "mma.sync.aligned.m16n8k16.row.col.f32.bf16.bf16.f32 "
        "{%0,%1,%2,%3}, {%4,%5,%6,%7}, {%8,%9}, {%0,%1,%2,%3};"
        : "+f"(c0), "+f"(c1), "+f"(c2), "+f"(c3)
        : "r"(a0), "r"(a1), "r"(a2), "r"(a3), "r"(b0), "r"(b1));
}

// =========================================================================
// Kernel 1: HMMA x_proj (unchanged from R7 pass). grid (16, 256).
// =========================================================================
#define APITCH 36
#define PLW (128 * APITCH)

__global__ __launch_bounds__(256, 1) void xproj_kernel(
    const float* __restrict__ src, const float* __restrict__ Wih,
    const float* __restrict__ bih, const float* __restrict__ bhh)
{
    extern __shared__ u32 smw[];
    u32* Ah = smw;
    u32* Al = smw + PLW;
    u32* Bh = smw + 2 * PLW;
    u32* Bl = smw + 3 * PLW;

    const int tid = threadIdx.x;
    if (blockIdx.x == 0 && blockIdx.y == 0) {
        uint4 z = {0, 0, 0, 0};
        const int n16 = (int)(sizeof(g_hpk) / 16);
        for (int i = tid; i < n16; i += 256) ((uint4*)g_hpk)[i] = z;
        for (int i = tid; i < NCTA * 8; i += 256) g_flags[i] = 0u;
    }

    const int g0 = blockIdx.x * 128;
    const int n0 = blockIdx.y * 128;
    const int warp = tid >> 5, lane = tid & 31;
    const int wm = warp & 3, wn = warp >> 2;
    const int g_ = lane >> 2, t_ = lane & 3;

    float C[2][8][4];
#pragma unroll
    for (int mt = 0; mt < 2; mt++)
#pragma unroll
        for (int nt = 0; nt < 8; nt++)
#pragma unroll
            for (int r = 0; r < 4; r++) C[mt][nt][r] = 0.0f;

    for (int kc = 0; kc < 8; kc++) {
        const int c0 = kc * 64;
#pragma unroll
        for (int i = 0; i < 8; i++) {
            int idx = tid + i * 256;
            int row = idx >> 4, cq = idx & 15;
            float4 w = *(const float4*)(Wih + (size_t)(g0 + row) * HH + c0 + cq * 4);
            float hx = __bfloat162float(__float2bfloat16(w.x));
            float hy = __bfloat162float(__float2bfloat16(w.y));
            float hz = __bfloat162float(__float2bfloat16(w.z));
            float hw = __bfloat162float(__float2bfloat16(w.w));
            *(uint2*)(Ah + row * APITCH + cq * 2) =
                make_uint2(pack_bf2(w.x, w.y), pack_bf2(w.z, w.w));
            *(uint2*)(Al + row * APITCH + cq * 2) =
                make_uint2(pack_bf2(w.x - hx, w.y - hy), pack_bf2(w.z - hz, w.w - hw));
        }
#pragma unroll
        for (int i = 0; i < 8; i++) {
            int idx = tid + i * 256;
            int n = idx >> 4, cq = idx & 15;
            int N = n0 + n, b = N & 31, tt = N >> 5;
            float4 w = *(const float4*)(src + ((size_t)b * TT + tt) * HH + c0 + cq * 4);
            float hx = __bfloat162float(__float2bfloat16(w.x));
            float hy = __bfloat162float(__float2bfloat16(w.y));
            float hz = __bfloat162float(__float2bfloat16(w.z));
            float hw = __bfloat162float(__float2bfloat16(w.w));
            *(uint2*)(Bh + n * APITCH + cq * 2) =
                make_uint2(pack_bf2(w.x, w.y), pack_bf2(w.z, w.w));
            *(uint2*)(Bl + n * APITCH + cq * 2) =
                make_uint2(pack_bf2(w.x - hx, w.y - hy), pack_bf2(w.z - hz, w.w - hw));
        }
        __syncthreads();

#pragma unroll
        for (int kt = 0; kt < 4; kt++) {
            const int wbase = kt * 8 + t_;
            u32 ah[2][4], al[2][4];
#pragma unroll
            for (int mt = 0; mt < 2; mt++) {
                int ra = wm * 32 + mt * 16 + g_;
                ah[mt][0] = Ah[ra * APITCH + wbase];
                ah[mt][1] = Ah[(ra + 8) * APITCH + wbase];
                ah[mt][2] = Ah[ra * APITCH + wbase + 4];
                ah[mt][3] = Ah[(ra + 8) * APITCH + wbase + 4];
                al[mt][0] = Al[ra * APITCH + wbase];
                al[mt][1] = Al[(ra + 8) * APITCH + wbase];
                al[mt][2] = Al[ra * APITCH + wbase + 4];
                al[mt][3] = Al[(ra + 8) * APITCH + wbase + 4];
            }
#pragma unroll
            for (int nt = 0; nt < 8; nt++) {
                int nc = wn * 64 + nt * 8 + g_;
                u32 b0h = Bh[nc * APITCH + wbase];
                u32 b1h = Bh[nc * APITCH + wbase + 4];
                u32 b0l = Bl[nc * APITCH + wbase];
                u32 b1l = Bl[nc * APITCH + wbase + 4];
#pragma unroll
                for (int mt = 0; mt < 2; mt++) {
                    mma16816(C[mt][nt][0], C[mt][nt][1], C[mt][nt][2], C[mt][nt][3],
                             ah[mt][0], ah[mt][1], ah[mt][2], ah[mt][3], b0h, b1h);
                    mma16816(C[mt][nt][0], C[mt][nt][1], C[mt][nt][2], C[mt][nt][3],
                             al[mt][0], al[mt][1], al[mt][2], al[mt][3], b0h, b1h);
                    mma16816(C[mt][nt][0], C[mt][nt][1], C[mt][nt][2], C[mt][nt][3],
                             ah[mt][0], ah[mt][1], ah[mt][2], ah[mt][3], b0l, b1l);
                }
            }
        }
        __syncthreads();
    }

#pragma unroll
    for (int mt = 0; mt < 2; mt++) {
        int r0 = g0 + wm * 32 + mt * 16 + g_;
        int r1 = r0 + 8;
        float bs0 = bih[r0] + bhh[r0];
        float bs1 = bih[r1] + bhh[r1];
        ull bias0 = pack2(bs0, bs0), bias1 = pack2(bs1, bs1);
#pragma unroll
        for (int nt = 0; nt < 8; nt++) {
            int N = n0 + wn * 64 + nt * 8 + 2 * t_;
            int tt = N >> 5, b = N & 31;
            *(ull*)(g_xp + ((size_t)tt * GG + r0) * BB + b)
                = fadd2(pack2(C[mt][nt][0], C[mt][nt][1]), bias0);
            *(ull*)(g_xp + ((size_t)tt * GG + r1) * BB + b)
                = fadd2(pack2(C[mt][nt][2], C[mt][nt][3]), bias1);
        }
    }
}

// =========================================================================
// Kernel 2: HMMA recurrence, 128 CTAs x 256 thr, M=16.
// B-fragments loaded DIRECTLY from L2 (__ldcg) with a kt software pipeline —
// no smem staging, no cp.async wait. smem = 20KB reduction buffer only.
// =========================================================================
__global__ __launch_bounds__(256, 1) void lstm_kernel(
    const int* __restrict__ lengths, const float* __restrict__ Whh,
    float* __restrict__ out)
{
    __shared__ float red_s[8 * 16 * 40];     // red[kw][m][40]

    const int tid  = threadIdx.x;
    const int cta  = blockIdx.x;
    const int kw   = tid >> 5;               // warp = K chunk [kw*64, +64)
    const int lane = tid & 31;
    const int g_   = lane >> 2;
    const int t_   = lane & 3;

    // ---- prologue: W fragments (hi, lo), rows m = gate*4 + unit
    u32 Ahi[4][4], Alo[4][4];
    {
        const float* p0 = Whh + (size_t)((g_ >> 2) * HH + cta * 4 + (g_ & 3)) * HH;
        const float* p1 = p0 + (size_t)2 * HH * HH;   // rows +8 => gates 2,3
#pragma unroll
        for (int kt = 0; kt < 4; kt++) {
            int k0 = kw * 64 + kt * 16 + 2 * t_;
            float2 vv[4] = { *(const float2*)(p0 + k0), *(const float2*)(p1 + k0),
                             *(const float2*)(p0 + k0 + 8), *(const float2*)(p1 + k0 + 8) };
#pragma unroll
            for (int r = 0; r < 4; r++) {
                float hx = __bfloat162float(__float2bfloat16(vv[r].x));
                float hy = __bfloat162float(__float2bfloat16(vv[r].y));
                Ahi[kt][r] = pack_bf2(vv[r].x, vv[r].y);
                Alo[kt][r] = pack_bf2(vv[r].x - hx, vv[r].y - hy);
            }
        }
    }

    // updater mapping (tid < 128): ub = batch, uu = unit
    const int ub = tid >> 2, uu = tid & 3;
    int   len = 0;
    float c_r = 0.0f, h_r = 0.0f;
    if (tid < 128) len = lengths[ub];

    for (int t = 0; t < TT; t++) {
        const int p = t & 1;

        // xg prefetch (in flight during poll)
        float xg0 = 0.f, xg1 = 0.f, xg2 = 0.f, xg3 = 0.f;
        if (tid < 128) {
            const float* xp = g_xp + ((size_t)t * GG + cta * 4 + uu) * BB + ub;
            xg0 = xp[0 * HH * BB];
            xg1 = xp[1 * HH * BB];
            xg2 = xp[2 * HH * BB];
            xg3 = xp[3 * HH * BB];
        }

        // grid barrier: all 128 CTAs published step t-1
        if (t > 0 && tid < NCTA) {
            const unsigned* f = &g_flags[tid * 8];
            unsigned v;
            do {
                asm volatile("ld.acquire.gpu.u32 %0, [%1];" : "=r"(v) : "l"(f) : "memory");
            } while (v < (unsigned)t);
        }
        __syncthreads();

        // ---- pipelined direct-L2 B loads + merged 3-term MMA
        const u32* hb = g_hpk[p];
        float C[4][4];
#pragma unroll
        for (int nt = 0; nt < 4; nt++)
#pragma unroll
            for (int r = 0; r < 4; r++) C[nt][r] = 0.0f;

        uint2 bA[2][4], bB[2][4];
        {
            const int k0 = kw * 64 + 2 * t_;
#pragma unroll
            for (int nt = 0; nt < 4; nt++) {
                const u32* pp = hb + (nt * 8 + g_) * PKP + k0;
                bA[0][nt] = __ldcg((const uint2*)pp);
                bB[0][nt] = __ldcg((const uint2*)(pp + 8));
            }
        }
#pragma unroll
        for (int kt = 0; kt < 4; kt++) {
            const int s = kt & 1;
            if (kt < 3) {
                const int k0 = kw * 64 + (kt + 1) * 16 + 2 * t_;
#pragma unroll
                for (int nt = 0; nt < 4; nt++) {
                    const u32* pp = hb + (nt * 8 + g_) * PKP + k0;
                    bA[1 - s][nt] = __ldcg((const uint2*)pp);
                    bB[1 - s][nt] = __ldcg((const uint2*)(pp + 8));
                }
            }
#pragma unroll
            for (int nt = 0; nt < 4; nt++) {
                u32 b0h = __byte_perm(bA[s][nt].x, bA[s][nt].y, 0x5410);
                u32 b1h = __byte_perm(bB[s][nt].x, bB[s][nt].y, 0x5410);
                u32 b0l = __byte_perm(bA[s][nt].x, bA[s][nt].y, 0x7632);
                u32 b1l = __byte_perm(bB[s][nt].x, bB[s][nt].y, 0x7632);
                mma16816(C[nt][0], C[nt][1], C[nt][2], C[nt][3],
                         Ahi[kt][0], Ahi[kt][1], Ahi[kt][2], Ahi[kt][3], b0h, b1h);
                mma16816(C[nt][0], C[nt][1], C[nt][2], C[nt][3],
                         Alo[kt][0], Alo[kt][1], Alo[kt][2], Alo[kt][3], b0h, b1h);
                mma16816(C[nt][0], C[nt][1], C[nt][2], C[nt][3],
                         Ahi[kt][0], Ahi[kt][1], Ahi[kt][2], Ahi[kt][3], b0l, b1l);
            }
        }

        // write k-partials: red[kw][m][40]
        {
            float* rw = red_s + kw * 16 * 40;
#pragma unroll
            for (int nt = 0; nt < 4; nt++) {
                int n = nt * 8 + 2 * t_;
                *(float2*)(rw + g_ * 40 + n)       = make_float2(C[nt][0], C[nt][1]);
                *(float2*)(rw + (g_ + 8) * 40 + n) = make_float2(C[nt][2], C[nt][3]);
            }
        }
        __syncthreads();

        // updaters: reduce 8 k-partials, gates, state, packed publish
        float out_val = 0.0f;
        if (tid < 128) {
            float s[4];
#pragma unroll
            for (int gt = 0; gt < 4; gt++) {
                int m = gt * 4 + uu;
                float a0 = 0.f, a1 = 0.f;
#pragma unroll
                for (int w = 0; w < 8; w += 2) {
                    a0 += red_s[(w * 16 + m) * 40 + ub];
                    a1 += red_s[((w + 1) * 16 + m) * 40 + ub];
                }
                s[gt] = a0 + a1;
            }
            float gi_ = sigm(xg0 + s[0]);
            float gf  = sigm(xg1 + s[1]);
            float gg  = tanh_(xg2 + s[2]);
            float go  = sigm(xg3 + s[3]);
            float cn = gf * c_r + gi_ * gg;
            float hn = go * tanh_(cn);
            bool valid = (t < len);
            if (valid) { c_r = cn; h_r = hn; }
            out_val = valid ? hn : 0.0f;

            // packed (hi, lo) publish: ONE 4B store
            __nv_bfloat16 hh = __float2bfloat16(h_r);
            float rlo = h_r - __bfloat162float(hh);
            u32 word = (u32)__bfloat16_as_ushort(hh)
                     | ((u32)__bfloat16_as_ushort(__float2bfloat16(rlo)) << 16);
            g_hpk[1 - p][ub * PKP + cta * 4 + uu] = word;

            // updater-warps-only barrier, then release (MMA warps not held)
            asm volatile("bar.sync 1, 128;" ::: "memory");
            if (tid == 0) {
                asm volatile("st.release.gpu.u32 [%0], %1;"
                             :: "l"(&g_flags[cta * 8]), "r"((unsigned)(t + 1)) : "memory");
            }
            out[((size_t)t * BB + ub) * HH + cta * 4 + uu] = out_val;
        }
    }

    // final hT, cT
    if (tid < 128) {
        size_t base = (size_t)TT * BB * HH;
        out[base + (size_t)ub * HH + cta * 4 + uu] = h_r;
        out[base + (size_t)BB * HH + (size_t)ub * HH + cta * 4 + uu] = c_r;
    }
}

// =========================================================================
extern "C" void kernel_launch(void* const* d_in, const int* in_sizes, int n_in,
                              void* d_out, int out_size) {
    const float* src  = (const float*)d_in[0];
    const int*   lens = (const int*)d_in[1];
    const float* Wih  = (const float*)d_in[2];
    const float* Whh  = (const float*)d_in[3];
    const float* bih  = (const float*)d_in[4];
    const float* bhh  = (const float*)d_in[5];
    float* out = (float*)d_out;

    const int smem_xproj = 4 * PLW * 4;          // 73,728 B
    cudaFuncSetAttribute(xproj_kernel, cudaFuncAttributeMaxDynamicSharedMemorySize, smem_xproj);

    dim3 grid(16, 256);
    xproj_kernel<<<grid, 256, smem_xproj>>>(src, Wih, bih, bhh);
    lstm_kernel<<<NCTA, 256>>>(lens, Whh, out);
}

// round 9
// speedup vs baseline: 1.1306x; 1.1306x over previous
#include <cuda_runtime.h>
#include <cuda_bf16.h>
#include <cstdint>
#include <cstddef>

typedef unsigned long long ull;
typedef unsigned int u32;

#define BB 32
#define TT 1024
#define HH 512
#define GG 2048
#define NCTA 128            // lstm CTAs
#define HPW 260             // half-image pitch (words): 256 + 4
#define HALF_B (32 * HPW * 4)   // 33280 bytes per half-image

// ---------------- device scratch (allocations are forbidden) ----------------
__device__ __align__(16) float g_xp[(size_t)TT * GG * BB];     // x_proj[t][g][b]
__device__ __align__(16) u32 g_hpk[2][2][32 * HPW];            // [phase][khalf][b][kloc] packed
__device__ __align__(128) unsigned g_flags[NCTA * 8];

// ---------------- helpers ----------------
__device__ __forceinline__ ull fadd2(ull a, ull b) {
    ull d; asm("add.rn.f32x2 %0, %1, %2;" : "=l"(d) : "l"(a), "l"(b)); return d;
}
__device__ __forceinline__ ull pack2(float x, float y) {
    ull d; asm("mov.b64 %0, {%1, %2};" : "=l"(d) : "f"(x), "f"(y)); return d;
}
__device__ __forceinline__ float sigm(float x) { return __fdividef(1.0f, 1.0f + __expf(-x)); }
__device__ __forceinline__ float tanh_(float x) { return 1.0f - __fdividef(2.0f, __expf(2.0f * x) + 1.0f); }

__device__ __forceinline__ u32 smem_u32(const void* p) {
    u32 a; asm("{ .reg .u64 t; cvta.to.shared.u64 t, %1; cvt.u32.u64 %0, t; }" : "=r"(a) : "l"(p)); return a;
}
__device__ __forceinline__ u32 pack_bf2(float a, float b) {
    return (u32)__bfloat16_as_ushort(__float2bfloat16(a))
         | ((u32)__bfloat16_as_ushort(__float2bfloat16(b)) << 16);
}
__device__ __forceinline__ void mma16816(float& c0, float& c1, float& c2, float& c3,
                                         u32 a0, u32 a1, u32 a2, u32 a3, u32 b0, u32 b1) {
    asm volatile(
        "mma.sync.aligned.m16n8k16.row.col.f32.bf16.bf16.f32 "
        "{%0,%1,%2,%3}, {%4,%5,%6,%7}, {%8,%9}, {%0,%1,%2,%3};"
        : "+f"(c0), "+f"(c1), "+f"(c2), "+f"(c3)
        : "r"(a0), "r"(a1), "r"(a2), "r"(a3), "r"(b0), "r"(b1));
}

#define MBAR_INIT(mbar, cnt) \
    asm volatile("mbarrier.init.shared.b64 [%0], %1;" :: "r"((u32)(mbar)), "r"((u32)(cnt)) : "memory")
#define MBAR_EXPECT_TX(mbar, bytes) \
    asm volatile("mbarrier.arrive.expect_tx.shared.b64 _, [%0], %1;" \
        :: "r"((u32)(mbar)), "r"((u32)(bytes)) : "memory")
#define MBAR_WAIT(mbar, par) do { \
    u32 _m = (u32)(mbar), _p = (u32)(par); \
    asm volatile("{\n\t.reg .pred P1;\n\t" \
        "WL_%=:\n\t" \
        "mbarrier.try_wait.parity.acquire.cta.shared::cta.b64 P1, [%0], %1, 0x989680;\n\t" \
        "@P1 bra.uni WD_%=;\n\t" \
        "bra.uni WL_%=;\n\tWD_%=:\n\t}" \
        :: "r"(_m), "r"(_p) : "memory"); \
} while (0)
__device__ __forceinline__ void bulk_cp(u32 dst_smem, const void* src, u32 bytes, u32 mbar) {
    asm volatile(
        "cp.async.bulk.shared::cta.global.mbarrier::complete_tx::bytes [%0], [%1], %2, [%3];"
        :: "r"(dst_smem), "l"(src), "r"(bytes), "r"(mbar) : "memory");
}

// =========================================================================
// Kernel 1: HMMA x_proj (unchanged structure from R7 pass). grid (16, 256).
// =========================================================================
#define APITCH 36
#define PLW (128 * APITCH)

__global__ __launch_bounds__(256, 1) void xproj_kernel(
    const float* __restrict__ src, const float* __restrict__ Wih,
    const float* __restrict__ bih, const float* __restrict__ bhh)
{
    extern __shared__ u32 smw[];
    u32* Ah = smw;
    u32* Al = smw + PLW;
    u32* Bh = smw + 2 * PLW;
    u32* Bl = smw + 3 * PLW;

    const int tid = threadIdx.x;
    if (blockIdx.x == 0 && blockIdx.y == 0) {
        uint4 z = {0, 0, 0, 0};
        const int n16 = (int)(sizeof(g_hpk) / 16);
        for (int i = tid; i < n16; i += 256) ((uint4*)g_hpk)[i] = z;
        for (int i = tid; i < NCTA * 8; i += 256) g_flags[i] = 0u;
    }

    const int g0 = blockIdx.x * 128;
    const int n0 = blockIdx.y * 128;
    const int warp = tid >> 5, lane = tid & 31;
    const int wm = warp & 3, wn = warp >> 2;
    const int g_ = lane >> 2, t_ = lane & 3;

    float C[2][8][4];
#pragma unroll
    for (int mt = 0; mt < 2; mt++)
#pragma unroll
        for (int nt = 0; nt < 8; nt++)
#pragma unroll
            for (int r = 0; r < 4; r++) C[mt][nt][r] = 0.0f;

    for (int kc = 0; kc < 8; kc++) {
        const int c0 = kc * 64;
#pragma unroll
        for (int i = 0; i < 8; i++) {
            int idx = tid + i * 256;
            int row = idx >> 4, cq = idx & 15;
            float4 w = *(const float4*)(Wih + (size_t)(g0 + row) * HH + c0 + cq * 4);
            float hx = __bfloat162float(__float2bfloat16(w.x));
            float hy = __bfloat162float(__float2bfloat16(w.y));
            float hz = __bfloat162float(__float2bfloat16(w.z));
            float hw = __bfloat162float(__float2bfloat16(w.w));
            *(uint2*)(Ah + row * APITCH + cq * 2) =
                make_uint2(pack_bf2(w.x, w.y), pack_bf2(w.z, w.w));
            *(uint2*)(Al + row * APITCH + cq * 2) =
                make_uint2(pack_bf2(w.x - hx, w.y - hy), pack_bf2(w.z - hz, w.w - hw));
        }
#pragma unroll
        for (int i = 0; i < 8; i++) {
            int idx = tid + i * 256;
            int n = idx >> 4, cq = idx & 15;
            int N = n0 + n, b = N & 31, tt = N >> 5;
            float4 w = *(const float4*)(src + ((size_t)b * TT + tt) * HH + c0 + cq * 4);
            float hx = __bfloat162float(__float2bfloat16(w.x));
            float hy = __bfloat162float(__float2bfloat16(w.y));
            float hz = __bfloat162float(__float2bfloat16(w.z));
            float hw = __bfloat162float(__float2bfloat16(w.w));
            *(uint2*)(Bh + n * APITCH + cq * 2) =
                make_uint2(pack_bf2(w.x, w.y), pack_bf2(w.z, w.w));
            *(uint2*)(Bl + n * APITCH + cq * 2) =
                make_uint2(pack_bf2(w.x - hx, w.y - hy), pack_bf2(w.z - hz, w.w - hw));
        }
        __syncthreads();

#pragma unroll
        for (int kt = 0; kt < 4; kt++) {
            const int wbase = kt * 8 + t_;
            u32 ah[2][4], al[2][4];
#pragma unroll
            for (int mt = 0; mt < 2; mt++) {
                int ra = wm * 32 + mt * 16 + g_;
                ah[mt][0] = Ah[ra * APITCH + wbase];
                ah[mt][1] = Ah[(ra + 8) * APITCH + wbase];
                ah[mt][2] = Ah[ra * APITCH + wbase + 4];
                ah[mt][3] = Ah[(ra + 8) * APITCH + wbase + 4];
                al[mt][0] = Al[ra * APITCH + wbase];
                al[mt][1] = Al[(ra + 8) * APITCH + wbase];
                al[mt][2] = Al[ra * APITCH + wbase + 4];
                al[mt][3] = Al[(ra + 8) * APITCH + wbase + 4];
            }
#pragma unroll
            for (int nt = 0; nt < 8; nt++) {
                int nc = wn * 64 + nt * 8 + g_;
                u32 b0h = Bh[nc * APITCH + wbase];
                u32 b1h = Bh[nc * APITCH + wbase + 4];
                u32 b0l = Bl[nc * APITCH + wbase];
                u32 b1l = Bl[nc * APITCH + wbase + 4];
#pragma unroll
                for (int mt = 0; mt < 2; mt++) {
                    mma16816(C[mt][nt][0], C[mt][nt][1], C[mt][nt][2], C[mt][nt][3],
                             ah[mt][0], ah[mt][1], ah[mt][2], ah[mt][3], b0h, b1h);
                    mma16816(C[mt][nt][0], C[mt][nt][1], C[mt][nt][2], C[mt][nt][3],
                             al[mt][0], al[mt][1], al[mt][2], al[mt][3], b0h, b1h);
                    mma16816(C[mt][nt][0], C[mt][nt][1], C[mt][nt][2], C[mt][nt][3],
                             ah[mt][0], ah[mt][1], ah[mt][2], ah[mt][3], b0l, b1l);
                }
            }
        }
        __syncthreads();
    }

#pragma unroll
    for (int mt = 0; mt < 2; mt++) {
        int r0 = g0 + wm * 32 + mt * 16 + g_;
        int r1 = r0 + 8;
        float bs0 = bih[r0] + bhh[r0];
        float bs1 = bih[r1] + bhh[r1];
        ull bias0 = pack2(bs0, bs0), bias1 = pack2(bs1, bs1);
#pragma unroll
        for (int nt = 0; nt < 8; nt++) {
            int N = n0 + wn * 64 + nt * 8 + 2 * t_;
            int tt = N >> 5, b = N & 31;
            *(ull*)(g_xp + ((size_t)tt * GG + r0) * BB + b)
                = fadd2(pack2(C[mt][nt][0], C[mt][nt][1]), bias0);
            *(ull*)(g_xp + ((size_t)tt * GG + r1) * BB + b)
                = fadd2(pack2(C[mt][nt][2], C[mt][nt][3]), bias1);
        }
    }
}

// =========================================================================
// Kernel 2: HMMA recurrence with cp.async.bulk staging.
// smem: [0:8) mbar0, [8:16) mbar1, [128: +33280) half0, then half1, then red.
// =========================================================================
#define SM_IMG0 128
#define SM_IMG1 (128 + HALF_B)
#define SM_RED  (128 + 2 * HALF_B)
#define SM_TOT_L (SM_RED + 8 * 16 * 40 * 4)

__global__ __launch_bounds__(256, 1) void lstm_kernel(
    const int* __restrict__ lengths, const float* __restrict__ Whh,
    float* __restrict__ out)
{
    extern __shared__ char smc[];
    const u32 sb = smem_u32(smc);
    float* red_s = (float*)(smc + SM_RED);

    const int tid  = threadIdx.x;
    const int cta  = blockIdx.x;
    const int kw   = tid >> 5;               // warp = K chunk [kw*64, +64)
    const int lane = tid & 31;
    const int g_   = lane >> 2;
    const int t_   = lane & 3;
    const int half = kw >> 2;
    const u32* img = (const u32*)(smc + (half ? SM_IMG1 : SM_IMG0));
    const u32 mb_own = sb + (half ? 8 : 0);

    // ---- prologue: W fragments (hi, lo), rows m = gate*4 + unit
    u32 Ahi[4][4], Alo[4][4];
    {
        const float* p0 = Whh + (size_t)((g_ >> 2) * HH + cta * 4 + (g_ & 3)) * HH;
        const float* p1 = p0 + (size_t)2 * HH * HH;   // rows +8 => gates 2,3
#pragma unroll
        for (int kt = 0; kt < 4; kt++) {
            int k0 = kw * 64 + kt * 16 + 2 * t_;
            float2 vv[4] = { *(const float2*)(p0 + k0), *(const float2*)(p1 + k0),
                             *(const float2*)(p0 + k0 + 8), *(const float2*)(p1 + k0 + 8) };
#pragma unroll
            for (int r = 0; r < 4; r++) {
                float hx = __bfloat162float(__float2bfloat16(vv[r].x));
                float hy = __bfloat162float(__float2bfloat16(vv[r].y));
                Ahi[kt][r] = pack_bf2(vv[r].x, vv[r].y);
                Alo[kt][r] = pack_bf2(vv[r].x - hx, vv[r].y - hy);
            }
        }
    }

    if (tid == 0) { MBAR_INIT(sb, 1); MBAR_INIT(sb + 8, 1); }
    __syncthreads();

    // updater mapping (tid < 128): ub = batch, uu = unit
    const int ub = tid >> 2, uu = tid & 3;
    int   len = 0;
    float c_r = 0.0f, h_r = 0.0f;
    if (tid < 128) len = lengths[ub];
    const int kk_pub = cta * 4 + uu;                 // published unit index
    const int pub_half = kk_pub >> 8;
    const int pub_off  = ub * HPW + (kk_pub & 255);

    for (int t = 0; t < TT; t++) {
        const int p = t & 1;

        // xg prefetch (in flight during poll)
        float xg0 = 0.f, xg1 = 0.f, xg2 = 0.f, xg3 = 0.f;
        if (tid < 128) {
            const float* xp = g_xp + ((size_t)t * GG + cta * 4 + uu) * BB + ub;
            xg0 = xp[0 * HH * BB];
            xg1 = xp[1 * HH * BB];
            xg2 = xp[2 * HH * BB];
            xg3 = xp[3 * HH * BB];
        }

        // grid barrier: all 128 CTAs published step t-1
        if (t > 0 && tid < NCTA) {
            const unsigned* f = &g_flags[tid * 8];
            unsigned v;
            do {
                asm volatile("ld.acquire.gpu.u32 %0, [%1];" : "=r"(v) : "l"(f) : "memory");
            } while (v < (unsigned)t);
        }
        __syncthreads();

        // ---- stage both half-images with TWO bulk copies (DMA, no LSU loop)
        if (tid == 0) {
            MBAR_EXPECT_TX(sb, HALF_B);
            bulk_cp(sb + SM_IMG0, g_hpk[p][0], HALF_B, sb);
            MBAR_EXPECT_TX(sb + 8, HALF_B);
            bulk_cp(sb + SM_IMG1, g_hpk[p][1], HALF_B, sb + 8);
        }
        MBAR_WAIT(mb_own, t & 1);

        // ---- merged 3-term MMA from own half-image
        float C[4][4];
#pragma unroll
        for (int nt = 0; nt < 4; nt++)
#pragma unroll
            for (int r = 0; r < 4; r++) C[nt][r] = 0.0f;

        const int kbase = (kw & 3) * 64 + 2 * t_;
#pragma unroll
        for (int kt = 0; kt < 4; kt++) {
            const int k0 = kbase + kt * 16;
#pragma unroll
            for (int nt = 0; nt < 4; nt++) {
                const u32* pp = img + (nt * 8 + g_) * HPW + k0;
                uint2 wA = *(const uint2*)pp;
                uint2 wB = *(const uint2*)(pp + 8);
                u32 b0h = __byte_perm(wA.x, wA.y, 0x5410);
                u32 b1h = __byte_perm(wB.x, wB.y, 0x5410);
                u32 b0l = __byte_perm(wA.x, wA.y, 0x7632);
                u32 b1l = __byte_perm(wB.x, wB.y, 0x7632);
                mma16816(C[nt][0], C[nt][1], C[nt][2], C[nt][3],
                         Ahi[kt][0], Ahi[kt][1], Ahi[kt][2], Ahi[kt][3], b0h, b1h);
                mma16816(C[nt][0], C[nt][1], C[nt][2], C[nt][3],
                         Alo[kt][0], Alo[kt][1], Alo[kt][2], Alo[kt][3], b0h, b1h);
                mma16816(C[nt][0], C[nt][1], C[nt][2], C[nt][3],
                         Ahi[kt][0], Ahi[kt][1], Ahi[kt][2], Ahi[kt][3], b0l, b1l);
            }
        }

        // write k-partials: red[kw][m][40]
        {
            float* rw = red_s + kw * 16 * 40;
#pragma unroll
            for (int nt = 0; nt < 4; nt++) {
                int n = nt * 8 + 2 * t_;
                *(float2*)(rw + g_ * 40 + n)       = make_float2(C[nt][0], C[nt][1]);
                *(float2*)(rw + (g_ + 8) * 40 + n) = make_float2(C[nt][2], C[nt][3]);
            }
        }
        __syncthreads();

        // updaters: reduce 8 k-partials, gates, state, packed publish
        if (tid < 128) {
            float s[4];
#pragma unroll
            for (int gt = 0; gt < 4; gt++) {
                int m = gt * 4 + uu;
                float a0 = 0.f, a1 = 0.f;
#pragma unroll
                for (int w = 0; w < 8; w += 2) {
                    a0 += red_s[(w * 16 + m) * 40 + ub];
                    a1 += red_s[((w + 1) * 16 + m) * 40 + ub];
                }
                s[gt] = a0 + a1;
            }
            float gi_ = sigm(xg0 + s[0]);
            float gf  = sigm(xg1 + s[1]);
            float gg  = tanh_(xg2 + s[2]);
            float go  = sigm(xg3 + s[3]);
            float cn = gf * c_r + gi_ * gg;
            float hn = go * tanh_(cn);
            bool valid = (t < len);
            if (valid) { c_r = cn; h_r = hn; }
            float out_val = valid ? hn : 0.0f;

            // packed (hi, lo) publish: ONE 4B store
            __nv_bfloat16 hh = __float2bfloat16(h_r);
            float rlo = h_r - __bfloat162float(hh);
            u32 word = (u32)__bfloat16_as_ushort(hh)
                     | ((u32)__bfloat16_as_ushort(__float2bfloat16(rlo)) << 16);
            g_hpk[1 - p][pub_half][pub_off] = word;

            // updater-warps-only barrier, then release (MMA warps not held)
            asm volatile("bar.sync 1, 128;" ::: "memory");
            if (tid == 0) {
                asm volatile("st.release.gpu.u32 [%0], %1;"
                             :: "l"(&g_flags[cta * 8]), "r"((unsigned)(t + 1)) : "memory");
            }
            out[((size_t)t * BB + ub) * HH + cta * 4 + uu] = out_val;
        }
    }

    // final hT, cT
    if (tid < 128) {
        size_t base = (size_t)TT * BB * HH;
        out[base + (size_t)ub * HH + cta * 4 + uu] = h_r;
        out[base + (size_t)BB * HH + (size_t)ub * HH + cta * 4 + uu] = c_r;
    }
}

// =========================================================================
extern "C" void kernel_launch(void* const* d_in, const int* in_sizes, int n_in,
                              void* d_out, int out_size) {
    const float* src  = (const float*)d_in[0];
    const int*   lens = (const int*)d_in[1];
    const float* Wih  = (const float*)d_in[2];
    const float* Whh  = (const float*)d_in[3];
    const float* bih  = (const float*)d_in[4];
    const float* bhh  = (const float*)d_in[5];
    float* out = (float*)d_out;

    const int smem_xproj = 4 * PLW * 4;          // 73,728 B
    cudaFuncSetAttribute(xproj_kernel, cudaFuncAttributeMaxDynamicSharedMemorySize, smem_xproj);
    cudaFuncSetAttribute(lstm_kernel,  cudaFuncAttributeMaxDynamicSharedMemorySize, SM_TOT_L);

    dim3 grid(16, 256);
    xproj_kernel<<<grid, 256, smem_xproj>>>(src, Wih, bih, bhh);
    lstm_kernel<<<NCTA, 256, SM_TOT_L>>>(lens, Whh, out);
}